// round 7
// baseline (speedup 1.0000x reference)
#include <cuda_runtime.h>
#include <cuda_bf16.h>
#include <cstdint>

// ---------------------------------------------------------------------------
// Problem constants
// ---------------------------------------------------------------------------
#define B_  2
#define N_  2048
#define M_  2048
#define D_  1024
#define H_  16
#define DH_ 64
#define ROWS_ (B_ * N_)   // 4096
// softmax in log2 domain: Q pre-scaled by DH^-0.5 * log2(e)
#define QSCALE_ 0.180336880111f

// ---------------------------------------------------------------------------
// Portable PTX helpers (sm_80+ features, valid at compute_103)
// ---------------------------------------------------------------------------
__device__ __forceinline__ uint32_t smem_u32(const void* p) {
    uint32_t a;
    asm("{ .reg .u64 t; cvta.to.shared.u64 t, %1; cvt.u32.u64 %0, t; }" : "=r"(a) : "l"(p));
    return a;
}
#define CP_ASYNC16(sa, ga) \
    asm volatile("cp.async.cg.shared.global [%0], [%1], 16;" :: "r"(sa), "l"(ga))
#define CP_COMMIT() asm volatile("cp.async.commit_group;" ::: "memory")
#define CP_WAIT(n)  asm volatile("cp.async.wait_group %0;" :: "n"(n) : "memory")

__device__ __forceinline__ void ldsm_x4(uint32_t* r, uint32_t addr) {
    asm volatile("ldmatrix.sync.aligned.m8n8.x4.shared.b16 {%0,%1,%2,%3}, [%4];"
                 : "=r"(r[0]), "=r"(r[1]), "=r"(r[2]), "=r"(r[3]) : "r"(addr));
}
__device__ __forceinline__ void ldsm_x4_t(uint32_t* r, uint32_t addr) {
    asm volatile("ldmatrix.sync.aligned.m8n8.x4.trans.shared.b16 {%0,%1,%2,%3}, [%4];"
                 : "=r"(r[0]), "=r"(r[1]), "=r"(r[2]), "=r"(r[3]) : "r"(addr));
}
__device__ __forceinline__ void mma16816(float* c, const uint32_t* a, const uint32_t* b) {
    asm volatile(
        "mma.sync.aligned.m16n8k16.row.col.f32.bf16.bf16.f32 "
        "{%0,%1,%2,%3}, {%4,%5,%6,%7}, {%8,%9}, {%0,%1,%2,%3};"
        : "+f"(c[0]), "+f"(c[1]), "+f"(c[2]), "+f"(c[3])
        : "r"(a[0]), "r"(a[1]), "r"(a[2]), "r"(a[3]), "r"(b[0]), "r"(b[1]));
}

// fast 2^x on fma/alu pipes (no MUFU): magic-number round + degree-5 poly
__device__ __forceinline__ float exp2f_fast(float x) {
    x = fmaxf(x, -100.0f);
    float t = x + 12582912.0f;                 // round-to-nearest integer
    float r = x - (t - 12582912.0f);           // r in [-0.5, 0.5]
    float p = 1.3333558146e-3f;
    p = fmaf(p, r, 9.6181291076e-3f);
    p = fmaf(p, r, 5.5504108664e-2f);
    p = fmaf(p, r, 2.4022650696e-1f);
    p = fmaf(p, r, 6.9314718056e-1f);
    p = fmaf(p, r, 1.0f);
    return __int_as_float(__float_as_int(p) + (__float_as_int(t) << 23));
}

// pack two floats into bf16x2 hi + bf16x2 lo (split)
__device__ __forceinline__ void pack_hl(float x, float y, uint32_t& h, uint32_t& lo) {
    __nv_bfloat162 hv = __floats2bfloat162_rn(x, y);
    float hx = __bfloat162float(hv.x), hy = __bfloat162float(hv.y);
    __nv_bfloat162 lv = __floats2bfloat162_rn(x - hx, y - hy);
    h  = *reinterpret_cast<uint32_t*>(&hv);
    lo = *reinterpret_cast<uint32_t*>(&lv);
}

// ---------------------------------------------------------------------------
// Scratch (__device__ globals)
// ---------------------------------------------------------------------------
__device__ __nv_bfloat16 g_qh[ROWS_ * D_], g_ql[ROWS_ * D_];   // Q (scaled) hi/lo
__device__ __nv_bfloat16 g_kh[ROWS_ * D_], g_kl[ROWS_ * D_];
__device__ __nv_bfloat16 g_vh[ROWS_ * D_], g_vl[ROWS_ * D_];
__device__ __nv_bfloat16 g_oh[ROWS_ * D_], g_ol[ROWS_ * D_];   // attention out hi/lo
__device__ __nv_bfloat16 g_xh[ROWS_ * D_], g_xl[ROWS_ * D_];
__device__ __nv_bfloat16 g_ch[ROWS_ * D_], g_cl[ROWS_ * D_];
__device__ __nv_bfloat16 g_wh[4][D_ * D_], g_wl[4][D_ * D_];   // q,k,v,o transposed [n][k]

// ---------------------------------------------------------------------------
// fp32 -> bf16 hi/lo split: x and ctx in one launch (blockIdx.y selects)
// ---------------------------------------------------------------------------
__global__ void split2_kernel(const float* __restrict__ a, const float* __restrict__ b,
                              __nv_bfloat16* __restrict__ ah, __nv_bfloat16* __restrict__ al,
                              __nv_bfloat16* __restrict__ bh, __nv_bfloat16* __restrict__ bl,
                              int n)
{
    int i = blockIdx.x * blockDim.x + threadIdx.x;
    if (i >= n) return;
    const float* s = blockIdx.y ? b : a;
    __nv_bfloat16* dh = blockIdx.y ? bh : ah;
    __nv_bfloat16* dl = blockIdx.y ? bl : al;
    float v = s[i];
    __nv_bfloat16 hv = __float2bfloat16(v);
    dh[i] = hv;
    dl[i] = __float2bfloat16(v - __bfloat162float(hv));
}

// fp32 W[k][n] -> bf16 hi/lo transposed out[n][k]; blockIdx.z selects weight
__global__ void wsplit_t_kernel(const float* __restrict__ W0, const float* __restrict__ W1,
                                const float* __restrict__ W2, const float* __restrict__ W3,
                                __nv_bfloat16* __restrict__ hi, __nv_bfloat16* __restrict__ lo)
{
    __shared__ float tile[32][33];
    const float* W = (blockIdx.z == 0) ? W0 : (blockIdx.z == 1) ? W1 : (blockIdx.z == 2) ? W2 : W3;
    size_t zo = (size_t)blockIdx.z * D_ * D_;
    int n0 = blockIdx.x * 32, k0 = blockIdx.y * 32;
    tile[threadIdx.y][threadIdx.x] = W[(size_t)(k0 + threadIdx.y) * D_ + n0 + threadIdx.x];
    __syncthreads();
    float a = tile[threadIdx.x][threadIdx.y];
    __nv_bfloat16 h = __float2bfloat16(a);
    size_t o = zo + (size_t)(n0 + threadIdx.y) * D_ + k0 + threadIdx.x;
    hi[o] = h;
    lo[o] = __float2bfloat16(a - __bfloat162float(h));
}

// ---------------------------------------------------------------------------
// HMMA GEMM: C[4096,1024] = A @ B^T (B stored [n][k]); bf16 split-3, fp32 acc
// CTA 128x128, 8 warps (32x64 warp tile), K-stage 32, cp.async double buffer.
// MODE 0: fp32 out + bias.  MODE 1: bf16 hi/lo out, scaled.
// ---------------------------------------------------------------------------
#define NSTG (D_ / 32)
#define ARR_STRIDE 10240
#define STAGE_STRIDE (4 * ARR_STRIDE)
#define GEMM_SMEM (2 * STAGE_STRIDE)

template <int MODE>
__global__ __launch_bounds__(256) void hmma_gemm(
    const __nv_bfloat16* __restrict__ Ah_g, const __nv_bfloat16* __restrict__ Al_g,
    const __nv_bfloat16* __restrict__ Bh_g, const __nv_bfloat16* __restrict__ Bl_g,
    const float* __restrict__ bias, float scale,
    float* __restrict__ Cf,
    __nv_bfloat16* __restrict__ Ch, __nv_bfloat16* __restrict__ Cl)
{
    extern __shared__ char smem[];
    const uint32_t sb = smem_u32(smem);
    const int t = threadIdx.x;
    const int l = t & 31;
    const int wid = t >> 5;
    const int row0 = blockIdx.y * 128;
    const int col0 = blockIdx.x * 128;
    const int wr0 = (wid & 3) * 32;
    const int wc0 = (wid >> 2) * 64;

    float acc[2][8][4];
    #pragma unroll
    for (int i = 0; i < 2; i++)
        #pragma unroll
        for (int j = 0; j < 8; j++)
            #pragma unroll
            for (int k = 0; k < 4; k++) acc[i][j][k] = 0.f;

    auto load_stage = [&](int s) {
        const int k0 = s * 32;
        const uint32_t sbase = sb + (s & 1) * STAGE_STRIDE;
        #pragma unroll
        for (int i = 0; i < 8; i++) {
            int idx = i * 256 + t;
            int arr = idx >> 9;
            int rem = idx & 511;
            int row = rem >> 2;
            int ch  = rem & 3;
            const __nv_bfloat16* g;
            if (arr == 0)      g = Ah_g + (size_t)(row0 + row) * D_ + k0 + ch * 8;
            else if (arr == 1) g = Al_g + (size_t)(row0 + row) * D_ + k0 + ch * 8;
            else if (arr == 2) g = Bh_g + (size_t)(col0 + row) * D_ + k0 + ch * 8;
            else               g = Bl_g + (size_t)(col0 + row) * D_ + k0 + ch * 8;
            CP_ASYNC16(sbase + arr * ARR_STRIDE + row * 80 + ch * 16, g);
        }
        CP_COMMIT();
    };

    load_stage(0);

    for (int s = 0; s < NSTG; s++) {
        if (s + 1 < NSTG) { load_stage(s + 1); CP_WAIT(1); }
        else              { CP_WAIT(0); }
        __syncthreads();

        const uint32_t base = sb + (s & 1) * STAGE_STRIDE;
        const uint32_t aAh = base;
        const uint32_t aAl = base + ARR_STRIDE;
        const uint32_t aBh = base + 2 * ARR_STRIDE;
        const uint32_t aBl = base + 3 * ARR_STRIDE;

        #pragma unroll
        for (int ks = 0; ks < 2; ks++) {
            uint32_t ah[2][4], al[2][4], bh[8][2], bl[8][2];
            {
                int ar = wr0 + (l & 15);
                int ac = 2 * ks + (l >> 4);
                ldsm_x4(ah[0], aAh + (uint32_t)(ar * 80 + ac * 16));
                ldsm_x4(ah[1], aAh + (uint32_t)((ar + 16) * 80 + ac * 16));
                ldsm_x4(al[0], aAl + (uint32_t)(ar * 80 + ac * 16));
                ldsm_x4(al[1], aAl + (uint32_t)((ar + 16) * 80 + ac * 16));
            }
            {
                int br = wc0 + ((l >> 4) << 3) + (l & 7);
                int bc = 2 * ks + ((l >> 3) & 1);
                #pragma unroll
                for (int nt2 = 0; nt2 < 4; nt2++) {
                    uint32_t r[4];
                    ldsm_x4(r, aBh + (uint32_t)((br + nt2 * 16) * 80 + bc * 16));
                    bh[2 * nt2][0] = r[0]; bh[2 * nt2][1] = r[1];
                    bh[2 * nt2 + 1][0] = r[2]; bh[2 * nt2 + 1][1] = r[3];
                    ldsm_x4(r, aBl + (uint32_t)((br + nt2 * 16) * 80 + bc * 16));
                    bl[2 * nt2][0] = r[0]; bl[2 * nt2][1] = r[1];
                    bl[2 * nt2 + 1][0] = r[2]; bl[2 * nt2 + 1][1] = r[3];
                }
            }
            #pragma unroll
            for (int mt = 0; mt < 2; mt++)
                #pragma unroll
                for (int nt = 0; nt < 8; nt++) {
                    mma16816(acc[mt][nt], ah[mt], bh[nt]);
                    mma16816(acc[mt][nt], ah[mt], bl[nt]);
                    mma16816(acc[mt][nt], al[mt], bh[nt]);
                }
        }
        __syncthreads();
    }

    #pragma unroll
    for (int mt = 0; mt < 2; mt++)
        #pragma unroll
        for (int nt = 0; nt < 8; nt++) {
            int m = row0 + wr0 + mt * 16 + (l >> 2);
            int n = col0 + wc0 + nt * 8 + (l & 3) * 2;
            if (MODE == 0) {
                float bx = 0.f, by = 0.f;
                if (bias != nullptr) { bx = bias[n]; by = bias[n + 1]; }
                *reinterpret_cast<float2*>(&Cf[(size_t)m * D_ + n]) =
                    make_float2(acc[mt][nt][0] + bx, acc[mt][nt][1] + by);
                *reinterpret_cast<float2*>(&Cf[(size_t)(m + 8) * D_ + n]) =
                    make_float2(acc[mt][nt][2] + bx, acc[mt][nt][3] + by);
            } else {
                uint32_t hh, ll;
                pack_hl(acc[mt][nt][0] * scale, acc[mt][nt][1] * scale, hh, ll);
                *reinterpret_cast<uint32_t*>(&Ch[(size_t)m * D_ + n]) = hh;
                *reinterpret_cast<uint32_t*>(&Cl[(size_t)m * D_ + n]) = ll;
                pack_hl(acc[mt][nt][2] * scale, acc[mt][nt][3] * scale, hh, ll);
                *reinterpret_cast<uint32_t*>(&Ch[(size_t)(m + 8) * D_ + n]) = hh;
                *reinterpret_cast<uint32_t*>(&Cl[(size_t)(m + 8) * D_ + n]) = ll;
            }
        }
}

// ---------------------------------------------------------------------------
// HMMA flash attention. CTA = 128 queries x one (b,h). 8 warps, 16 rows each.
// Key tiles of 64; K/V (hi+lo) double-buffered via cp.async.
// Scores in log2 domain (Q pre-scaled); exp2 via FMA polynomial.
// ---------------------------------------------------------------------------
#define AKT 64
#define KROW 144                 // 64 bf16 = 128B data, padded to 144B
#define KB (AKT * KROW)          // 9216
#define ASTG (4 * KB)            // 36864
#define ATT_SMEM (2 * ASTG)      // 73728
#define NSKV (M_ / AKT)          // 32

__global__ __launch_bounds__(256) void attn_mma()
{
    extern __shared__ char smem[];
    const uint32_t sb = smem_u32(smem);
    const int t = threadIdx.x;
    const int l = t & 31;
    const int w = t >> 5;
    const int q0 = blockIdx.x * 128;
    const int h  = blockIdx.y;
    const int b  = blockIdx.z;
    const size_t headoff = (size_t)h * DH_;

    // ---- stage Q (128x64 hi/lo) through smem, ldmatrix into registers
    #pragma unroll
    for (int i = 0; i < 4; i++) {
        int idx = i * 256 + t;          // 0..1023
        int row = idx >> 3, ch = idx & 7;
        size_t g = (size_t)(b * N_ + q0 + row) * D_ + headoff + ch * 8;
        CP_ASYNC16(sb + row * KROW + ch * 16, g_qh + g);
        CP_ASYNC16(sb + 18432 + row * KROW + ch * 16, g_ql + g);
    }
    CP_COMMIT();
    CP_WAIT(0);
    __syncthreads();

    uint32_t qh[4][4], ql[4][4];
    {
        int ar = w * 16 + (l & 15);
        #pragma unroll
        for (int ks = 0; ks < 4; ks++) {
            ldsm_x4(qh[ks], sb + (uint32_t)(ar * KROW + ks * 32 + (l >> 4) * 16));
            ldsm_x4(ql[ks], sb + 18432 + (uint32_t)(ar * KROW + ks * 32 + (l >> 4) * 16));
        }
    }
    __syncthreads();   // done reading Q region before KV pipeline overwrites it

    float o[8][4];
    #pragma unroll
    for (int j = 0; j < 8; j++)
        #pragma unroll
        for (int i = 0; i < 4; i++) o[j][i] = 0.f;
    float m0 = -1e30f, m1 = -1e30f, ls0 = 0.f, ls1 = 0.f;

    auto load_kv = [&](int s) {
        const int mk = s * AKT;
        const uint32_t base = sb + (s & 1) * ASTG;
        #pragma unroll
        for (int i = 0; i < 8; i++) {
            int arr = i >> 1;                       // 0:Kh 1:Kl 2:Vh 3:Vl
            int rem = (i & 1) * 256 + t;            // 0..511
            int row = rem >> 3, ch = rem & 7;
            size_t g = (size_t)(b * M_ + mk + row) * D_ + headoff + ch * 8;
            const __nv_bfloat16* src = (arr == 0) ? g_kh : (arr == 1) ? g_kl
                                      : (arr == 2) ? g_vh : g_vl;
            CP_ASYNC16(base + arr * KB + row * KROW + ch * 16, src + g);
        }
        CP_COMMIT();
    };

    load_kv(0);

    for (int s = 0; s < NSKV; s++) {
        if (s + 1 < NSKV) { load_kv(s + 1); CP_WAIT(1); }
        else              { CP_WAIT(0); }
        __syncthreads();

        const uint32_t kh = sb + (s & 1) * ASTG;
        const uint32_t kl = kh + KB;
        const uint32_t vh = kh + 2 * KB;
        const uint32_t vl = kh + 3 * KB;

        // ---- S = Qh*Kh + Qh*Kl + Ql*Kh  (128x64, per-warp 16x64)
        float sc[8][4];
        #pragma unroll
        for (int j = 0; j < 8; j++)
            #pragma unroll
            for (int i = 0; i < 4; i++) sc[j][i] = 0.f;

        #pragma unroll
        for (int ks = 0; ks < 4; ks++) {
            int br = ((l >> 4) << 3) + (l & 7);
            int bcb = ks * 32 + ((l >> 3) & 1) * 16;
            #pragma unroll
            for (int nt2 = 0; nt2 < 4; nt2++) {
                uint32_t rh[4], rl[4];
                ldsm_x4(rh, kh + (uint32_t)((nt2 * 16 + br) * KROW + bcb));
                ldsm_x4(rl, kl + (uint32_t)((nt2 * 16 + br) * KROW + bcb));
                mma16816(sc[2 * nt2],     qh[ks], rh + 0);
                mma16816(sc[2 * nt2 + 1], qh[ks], rh + 2);
                mma16816(sc[2 * nt2],     qh[ks], rl + 0);
                mma16816(sc[2 * nt2 + 1], qh[ks], rl + 2);
                mma16816(sc[2 * nt2],     ql[ks], rh + 0);
                mma16816(sc[2 * nt2 + 1], ql[ks], rh + 2);
            }
        }

        // ---- online softmax (log2 domain)
        float mx0 = -1e30f, mx1 = -1e30f;
        #pragma unroll
        for (int j = 0; j < 8; j++) {
            mx0 = fmaxf(mx0, fmaxf(sc[j][0], sc[j][1]));
            mx1 = fmaxf(mx1, fmaxf(sc[j][2], sc[j][3]));
        }
        mx0 = fmaxf(mx0, __shfl_xor_sync(0xffffffffu, mx0, 1));
        mx0 = fmaxf(mx0, __shfl_xor_sync(0xffffffffu, mx0, 2));
        mx1 = fmaxf(mx1, __shfl_xor_sync(0xffffffffu, mx1, 1));
        mx1 = fmaxf(mx1, __shfl_xor_sync(0xffffffffu, mx1, 2));
        float mn0 = fmaxf(m0, mx0), mn1 = fmaxf(m1, mx1);
        float c0 = exp2f_fast(m0 - mn0), c1 = exp2f_fast(m1 - mn1);
        m0 = mn0; m1 = mn1;

        float ps0 = 0.f, ps1 = 0.f;
        #pragma unroll
        for (int j = 0; j < 8; j++) {
            sc[j][0] = exp2f_fast(sc[j][0] - mn0); ps0 += sc[j][0];
            sc[j][1] = exp2f_fast(sc[j][1] - mn0); ps0 += sc[j][1];
            sc[j][2] = exp2f_fast(sc[j][2] - mn1); ps1 += sc[j][2];
            sc[j][3] = exp2f_fast(sc[j][3] - mn1); ps1 += sc[j][3];
        }
        ps0 += __shfl_xor_sync(0xffffffffu, ps0, 1);
        ps0 += __shfl_xor_sync(0xffffffffu, ps0, 2);
        ps1 += __shfl_xor_sync(0xffffffffu, ps1, 1);
        ps1 += __shfl_xor_sync(0xffffffffu, ps1, 2);
        ls0 = ls0 * c0 + ps0;
        ls1 = ls1 * c1 + ps1;
        #pragma unroll
        for (int j = 0; j < 8; j++) {
            o[j][0] *= c0; o[j][1] *= c0;
            o[j][2] *= c1; o[j][3] *= c1;
        }

        // ---- O += (Ph+Pl) @ (Vh+Vl)  (3 terms)
        #pragma unroll
        for (int kv = 0; kv < 4; kv++) {
            uint32_t aPh[4], aPl[4];
            pack_hl(sc[2 * kv][0],     sc[2 * kv][1],     aPh[0], aPl[0]);
            pack_hl(sc[2 * kv][2],     sc[2 * kv][3],     aPh[1], aPl[1]);
            pack_hl(sc[2 * kv + 1][0], sc[2 * kv + 1][1], aPh[2], aPl[2]);
            pack_hl(sc[2 * kv + 1][2], sc[2 * kv + 1][3], aPh[3], aPl[3]);
            int key = kv * 16 + ((l >> 3) & 1) * 8 + (l & 7);
            #pragma unroll
            for (int nd2 = 0; nd2 < 4; nd2++) {
                uint32_t vbh[4], vbl[4];
                uint32_t va = (uint32_t)(key * KROW + nd2 * 32 + (l >> 4) * 16);
                ldsm_x4_t(vbh, vh + va);
                ldsm_x4_t(vbl, vl + va);
                mma16816(o[2 * nd2],     aPh, vbh + 0);
                mma16816(o[2 * nd2 + 1], aPh, vbh + 2);
                mma16816(o[2 * nd2],     aPh, vbl + 0);
                mma16816(o[2 * nd2 + 1], aPh, vbl + 2);
                mma16816(o[2 * nd2],     aPl, vbh + 0);
                mma16816(o[2 * nd2 + 1], aPl, vbh + 2);
            }
        }
        __syncthreads();   // all warps done reading stage s before it is refilled
    }

    // ---- normalize + write bf16 hi/lo
    float inv0 = 1.f / ls0, inv1 = 1.f / ls1;
    int r0 = q0 + w * 16 + (l >> 2);
    int r1 = r0 + 8;
    size_t base0 = (size_t)(b * N_ + r0) * D_ + headoff;
    size_t base1 = (size_t)(b * N_ + r1) * D_ + headoff;
    #pragma unroll
    for (int nd = 0; nd < 8; nd++) {
        int c = nd * 8 + (l & 3) * 2;
        uint32_t hh, ll;
        pack_hl(o[nd][0] * inv0, o[nd][1] * inv0, hh, ll);
        *reinterpret_cast<uint32_t*>(&g_oh[base0 + c]) = hh;
        *reinterpret_cast<uint32_t*>(&g_ol[base0 + c]) = ll;
        pack_hl(o[nd][2] * inv1, o[nd][3] * inv1, hh, ll);
        *reinterpret_cast<uint32_t*>(&g_oh[base1 + c]) = hh;
        *reinterpret_cast<uint32_t*>(&g_ol[base1 + c]) = ll;
    }
}

// ---------------------------------------------------------------------------
// Launch
// ---------------------------------------------------------------------------
extern "C" void kernel_launch(void* const* d_in, const int* in_sizes, int n_in,
                              void* d_out, int out_size)
{
    const float* x   = (const float*)d_in[0];
    const float* ctx = (const float*)d_in[1];
    const float* Wq  = (const float*)d_in[2];
    const float* Wk  = (const float*)d_in[3];
    const float* Wv  = (const float*)d_in[4];
    const float* Wo  = (const float*)d_in[5];
    const float* bo  = (const float*)d_in[6];
    float* out = (float*)d_out;

    __nv_bfloat16 *qh, *ql, *kh, *kl, *vh, *vl, *oh, *ol, *xh, *xl, *ch, *cl, *wh, *wl;
    cudaGetSymbolAddress((void**)&qh, g_qh); cudaGetSymbolAddress((void**)&ql, g_ql);
    cudaGetSymbolAddress((void**)&kh, g_kh); cudaGetSymbolAddress((void**)&kl, g_kl);
    cudaGetSymbolAddress((void**)&vh, g_vh); cudaGetSymbolAddress((void**)&vl, g_vl);
    cudaGetSymbolAddress((void**)&oh, g_oh); cudaGetSymbolAddress((void**)&ol, g_ol);
    cudaGetSymbolAddress((void**)&xh, g_xh); cudaGetSymbolAddress((void**)&xl, g_xl);
    cudaGetSymbolAddress((void**)&ch, g_ch); cudaGetSymbolAddress((void**)&cl, g_cl);
    cudaGetSymbolAddress((void**)&wh, g_wh); cudaGetSymbolAddress((void**)&wl, g_wl);

    cudaFuncSetAttribute(hmma_gemm<0>, cudaFuncAttributeMaxDynamicSharedMemorySize, GEMM_SMEM);
    cudaFuncSetAttribute(hmma_gemm<1>, cudaFuncAttributeMaxDynamicSharedMemorySize, GEMM_SMEM);
    cudaFuncSetAttribute(attn_mma, cudaFuncAttributeMaxDynamicSharedMemorySize, ATT_SMEM);

    const int NE = ROWS_ * D_;
    const size_t WSZ = (size_t)D_ * D_;

    split2_kernel<<<dim3((NE + 255) / 256, 2), 256>>>(x, ctx, xh, xl, ch, cl, NE);
    wsplit_t_kernel<<<dim3(32, 32, 4), dim3(32, 32)>>>(Wq, Wk, Wv, Wo, wh, wl);

    dim3 ggrid(D_ / 128, ROWS_ / 128);
    hmma_gemm<1><<<ggrid, 256, GEMM_SMEM>>>(xh, xl, wh + 0 * WSZ, wl + 0 * WSZ,
                                            nullptr, QSCALE_, nullptr, qh, ql);
    hmma_gemm<1><<<ggrid, 256, GEMM_SMEM>>>(ch, cl, wh + 1 * WSZ, wl + 1 * WSZ,
                                            nullptr, 1.0f, nullptr, kh, kl);
    hmma_gemm<1><<<ggrid, 256, GEMM_SMEM>>>(ch, cl, wh + 2 * WSZ, wl + 2 * WSZ,
                                            nullptr, 1.0f, nullptr, vh, vl);

    attn_mma<<<dim3(N_ / 128, H_, B_), 256, ATT_SMEM>>>();

    hmma_gemm<0><<<ggrid, 256, GEMM_SMEM>>>(oh, ol, wh + 3 * WSZ, wl + 3 * WSZ,
                                            bo, 1.0f, out, nullptr, nullptr);
}

// round 8
// speedup vs baseline: 1.1180x; 1.1180x over previous
#include <cuda_runtime.h>
#include <cuda_bf16.h>
#include <cstdint>

// ---------------------------------------------------------------------------
// Problem constants
// ---------------------------------------------------------------------------
#define B_  2
#define N_  2048
#define M_  2048
#define D_  1024
#define H_  16
#define DH_ 64
#define ROWS_ (B_ * N_)   // 4096
#define QSCALE_ 0.180336880111f   // DH^-0.5 * log2(e)

// ---------------------------------------------------------------------------
// Portable PTX helpers (sm_80+ features, valid at compute_103)
// ---------------------------------------------------------------------------
__device__ __forceinline__ uint32_t smem_u32(const void* p) {
    uint32_t a;
    asm("{ .reg .u64 t; cvta.to.shared.u64 t, %1; cvt.u32.u64 %0, t; }" : "=r"(a) : "l"(p));
    return a;
}
#define CP_ASYNC16(sa, ga) \
    asm volatile("cp.async.cg.shared.global [%0], [%1], 16;" :: "r"(sa), "l"(ga))
#define CP_COMMIT() asm volatile("cp.async.commit_group;" ::: "memory")
#define CP_WAIT(n)  asm volatile("cp.async.wait_group %0;" :: "n"(n) : "memory")

__device__ __forceinline__ void ldsm_x4(uint32_t* r, uint32_t addr) {
    asm volatile("ldmatrix.sync.aligned.m8n8.x4.shared.b16 {%0,%1,%2,%3}, [%4];"
                 : "=r"(r[0]), "=r"(r[1]), "=r"(r[2]), "=r"(r[3]) : "r"(addr));
}
__device__ __forceinline__ void ldsm_x4_t(uint32_t* r, uint32_t addr) {
    asm volatile("ldmatrix.sync.aligned.m8n8.x4.trans.shared.b16 {%0,%1,%2,%3}, [%4];"
                 : "=r"(r[0]), "=r"(r[1]), "=r"(r[2]), "=r"(r[3]) : "r"(addr));
}
__device__ __forceinline__ void mma16816(float* c, const uint32_t* a, const uint32_t* b) {
    asm volatile(
        "mma.sync.aligned.m16n8k16.row.col.f32.bf16.bf16.f32 "
        "{%0,%1,%2,%3}, {%4,%5,%6,%7}, {%8,%9}, {%0,%1,%2,%3};"
        : "+f"(c[0]), "+f"(c[1]), "+f"(c[2]), "+f"(c[3])
        : "r"(a[0]), "r"(a[1]), "r"(a[2]), "r"(a[3]), "r"(b[0]), "r"(b[1]));
}

// fast 2^x on fma/alu pipes (no MUFU)
__device__ __forceinline__ float exp2f_fast(float x) {
    x = fmaxf(x, -100.0f);
    float t = x + 12582912.0f;
    float r = x - (t - 12582912.0f);
    float p = 1.3333558146e-3f;
    p = fmaf(p, r, 9.6181291076e-3f);
    p = fmaf(p, r, 5.5504108664e-2f);
    p = fmaf(p, r, 2.4022650696e-1f);
    p = fmaf(p, r, 6.9314718056e-1f);
    p = fmaf(p, r, 1.0f);
    return __int_as_float(__float_as_int(p) + (__float_as_int(t) << 23));
}

__device__ __forceinline__ void pack_hl(float x, float y, uint32_t& h, uint32_t& lo) {
    __nv_bfloat162 hv = __floats2bfloat162_rn(x, y);
    float hx = __bfloat162float(hv.x), hy = __bfloat162float(hv.y);
    __nv_bfloat162 lv = __floats2bfloat162_rn(x - hx, y - hy);
    h  = *reinterpret_cast<uint32_t*>(&hv);
    lo = *reinterpret_cast<uint32_t*>(&lv);
}

// ---------------------------------------------------------------------------
// Scratch
// ---------------------------------------------------------------------------
__device__ __nv_bfloat16 g_qh[ROWS_ * D_], g_ql[ROWS_ * D_];
__device__ __nv_bfloat16 g_kh[ROWS_ * D_], g_kl[ROWS_ * D_];
__device__ __nv_bfloat16 g_vh[ROWS_ * D_], g_vl[ROWS_ * D_];
__device__ __nv_bfloat16 g_oh[ROWS_ * D_], g_ol[ROWS_ * D_];
__device__ __nv_bfloat16 g_xh[ROWS_ * D_], g_xl[ROWS_ * D_];
__device__ __nv_bfloat16 g_ch[ROWS_ * D_], g_cl[ROWS_ * D_];
__device__ __nv_bfloat16 g_wh[4][D_ * D_], g_wl[4][D_ * D_];

// ---------------------------------------------------------------------------
// fp32 -> bf16 hi/lo splits
// ---------------------------------------------------------------------------
__global__ void split2_kernel(const float* __restrict__ a, const float* __restrict__ b,
                              __nv_bfloat16* __restrict__ ah, __nv_bfloat16* __restrict__ al,
                              __nv_bfloat16* __restrict__ bh, __nv_bfloat16* __restrict__ bl,
                              int n)
{
    int i = blockIdx.x * blockDim.x + threadIdx.x;
    if (i >= n) return;
    const float* s = blockIdx.y ? b : a;
    __nv_bfloat16* dh = blockIdx.y ? bh : ah;
    __nv_bfloat16* dl = blockIdx.y ? bl : al;
    float v = s[i];
    __nv_bfloat16 hv = __float2bfloat16(v);
    dh[i] = hv;
    dl[i] = __float2bfloat16(v - __bfloat162float(hv));
}

__global__ void wsplit_t_kernel(const float* __restrict__ W0, const float* __restrict__ W1,
                                const float* __restrict__ W2, const float* __restrict__ W3,
                                __nv_bfloat16* __restrict__ hi, __nv_bfloat16* __restrict__ lo)
{
    __shared__ float tile[32][33];
    const float* W = (blockIdx.z == 0) ? W0 : (blockIdx.z == 1) ? W1 : (blockIdx.z == 2) ? W2 : W3;
    size_t zo = (size_t)blockIdx.z * D_ * D_;
    int n0 = blockIdx.x * 32, k0 = blockIdx.y * 32;
    tile[threadIdx.y][threadIdx.x] = W[(size_t)(k0 + threadIdx.y) * D_ + n0 + threadIdx.x];
    __syncthreads();
    float a = tile[threadIdx.x][threadIdx.y];
    __nv_bfloat16 h = __float2bfloat16(a);
    size_t o = zo + (size_t)(n0 + threadIdx.y) * D_ + k0 + threadIdx.x;
    hi[o] = h;
    lo[o] = __float2bfloat16(a - __bfloat162float(h));
}

// ---------------------------------------------------------------------------
// HMMA GEMM v2: 128x128 CTA, 4 warps, 64x64 warp tile, K-stage 32,
// cp.async double buffer with single __syncthreads per stage.
// MODE 1: QKV fused (grid.z selects), bf16 hi/lo out. MODE 0: fp32 out + bias.
// ---------------------------------------------------------------------------
#define NSTG (D_ / 32)
#define ARR_STRIDE 10240                 // 128 rows * 80B
#define STAGE_STRIDE (4 * ARR_STRIDE)
#define GEMM_SMEM (2 * STAGE_STRIDE)     // 81920

template <int MODE>
__global__ __launch_bounds__(128, 2) void hmma_gemm(
    const __nv_bfloat16* __restrict__ Axh, const __nv_bfloat16* __restrict__ Axl,
    const __nv_bfloat16* __restrict__ Ach, const __nv_bfloat16* __restrict__ Acl,
    const __nv_bfloat16* __restrict__ whb, const __nv_bfloat16* __restrict__ wlb,
    const float* __restrict__ bias,
    float* __restrict__ Cf,
    __nv_bfloat16* __restrict__ Ch0, __nv_bfloat16* __restrict__ Cl0,
    __nv_bfloat16* __restrict__ Ch1, __nv_bfloat16* __restrict__ Cl1,
    __nv_bfloat16* __restrict__ Ch2, __nv_bfloat16* __restrict__ Cl2)
{
    extern __shared__ char smem[];
    const uint32_t sb = smem_u32(smem);
    const int t = threadIdx.x;
    const int l = t & 31;
    const int w = t >> 5;
    const int row0 = blockIdx.y * 128;
    const int col0 = blockIdx.x * 128;
    const int wr0 = (w & 1) * 64;
    const int wc0 = (w >> 1) * 64;
    const int z = blockIdx.z;

    const size_t WSZ = (size_t)D_ * D_;
    const __nv_bfloat16* Ah_g = (MODE == 0) ? Axh : (z == 0 ? Axh : Ach);
    const __nv_bfloat16* Al_g = (MODE == 0) ? Axl : (z == 0 ? Axl : Acl);
    const __nv_bfloat16* Bh_g = whb + (size_t)((MODE == 0) ? 3 : z) * WSZ;
    const __nv_bfloat16* Bl_g = wlb + (size_t)((MODE == 0) ? 3 : z) * WSZ;
    __nv_bfloat16* Ch = (z == 0) ? Ch0 : (z == 1) ? Ch1 : Ch2;
    __nv_bfloat16* Cl = (z == 0) ? Cl0 : (z == 1) ? Cl1 : Cl2;
    const float scale = (MODE == 1 && z == 0) ? QSCALE_ : 1.0f;

    float acc[4][8][4];
    #pragma unroll
    for (int i = 0; i < 4; i++)
        #pragma unroll
        for (int j = 0; j < 8; j++)
            #pragma unroll
            for (int k = 0; k < 4; k++) acc[i][j][k] = 0.f;

    auto load_stage = [&](int s) {
        const int k0 = s * 32;
        const uint32_t sbase = sb + (s & 1) * STAGE_STRIDE;
        #pragma unroll
        for (int i = 0; i < 16; i++) {
            int idx = i * 128 + t;        // 0..2047
            int arr = idx >> 9;           // 512 chunks per array
            int rem = idx & 511;
            int row = rem >> 2;
            int ch  = rem & 3;
            const __nv_bfloat16* g;
            if (arr == 0)      g = Ah_g + (size_t)(row0 + row) * D_ + k0 + ch * 8;
            else if (arr == 1) g = Al_g + (size_t)(row0 + row) * D_ + k0 + ch * 8;
            else if (arr == 2) g = Bh_g + (size_t)(col0 + row) * D_ + k0 + ch * 8;
            else               g = Bl_g + (size_t)(col0 + row) * D_ + k0 + ch * 8;
            CP_ASYNC16(sbase + arr * ARR_STRIDE + row * 80 + ch * 16, g);
        }
        CP_COMMIT();
    };

    load_stage(0);
    CP_WAIT(0);
    __syncthreads();

    for (int s = 0; s < NSTG; s++) {
        if (s + 1 < NSTG) load_stage(s + 1);

        const uint32_t base = sb + (s & 1) * STAGE_STRIDE;
        const uint32_t aAh = base;
        const uint32_t aAl = base + ARR_STRIDE;
        const uint32_t aBh = base + 2 * ARR_STRIDE;
        const uint32_t aBl = base + 3 * ARR_STRIDE;

        #pragma unroll
        for (int ks = 0; ks < 2; ks++) {
            uint32_t ah[4][4], al[4][4], bh[8][2], bl[8][2];
            const int arow = wr0 + (l & 15);
            const int acol = (2 * ks + (l >> 4)) * 16;
            #pragma unroll
            for (int mt = 0; mt < 4; mt++) {
                ldsm_x4(ah[mt], aAh + (uint32_t)((arow + 16 * mt) * 80 + acol));
                ldsm_x4(al[mt], aAl + (uint32_t)((arow + 16 * mt) * 80 + acol));
            }
            const int brow = wc0 + ((l >> 4) << 3) + (l & 7);
            const int bcol = (2 * ks + ((l >> 3) & 1)) * 16;
            #pragma unroll
            for (int nt2 = 0; nt2 < 4; nt2++) {
                uint32_t r[4];
                ldsm_x4(r, aBh + (uint32_t)((brow + nt2 * 16) * 80 + bcol));
                bh[2 * nt2][0] = r[0]; bh[2 * nt2][1] = r[1];
                bh[2 * nt2 + 1][0] = r[2]; bh[2 * nt2 + 1][1] = r[3];
                ldsm_x4(r, aBl + (uint32_t)((brow + nt2 * 16) * 80 + bcol));
                bl[2 * nt2][0] = r[0]; bl[2 * nt2][1] = r[1];
                bl[2 * nt2 + 1][0] = r[2]; bl[2 * nt2 + 1][1] = r[3];
            }
            #pragma unroll
            for (int mt = 0; mt < 4; mt++)
                #pragma unroll
                for (int nt = 0; nt < 8; nt++) {
                    mma16816(acc[mt][nt], ah[mt], bh[nt]);
                    mma16816(acc[mt][nt], ah[mt], bl[nt]);
                    mma16816(acc[mt][nt], al[mt], bh[nt]);
                }
        }

        if (s + 1 < NSTG) { CP_WAIT(0); __syncthreads(); }
    }

    #pragma unroll
    for (int mt = 0; mt < 4; mt++)
        #pragma unroll
        for (int nt = 0; nt < 8; nt++) {
            int m = row0 + wr0 + mt * 16 + (l >> 2);
            int n = col0 + wc0 + nt * 8 + (l & 3) * 2;
            if (MODE == 0) {
                float bx = bias[n], by = bias[n + 1];
                *reinterpret_cast<float2*>(&Cf[(size_t)m * D_ + n]) =
                    make_float2(acc[mt][nt][0] + bx, acc[mt][nt][1] + by);
                *reinterpret_cast<float2*>(&Cf[(size_t)(m + 8) * D_ + n]) =
                    make_float2(acc[mt][nt][2] + bx, acc[mt][nt][3] + by);
            } else {
                uint32_t hh, ll;
                pack_hl(acc[mt][nt][0] * scale, acc[mt][nt][1] * scale, hh, ll);
                *reinterpret_cast<uint32_t*>(&Ch[(size_t)m * D_ + n]) = hh;
                *reinterpret_cast<uint32_t*>(&Cl[(size_t)m * D_ + n]) = ll;
                pack_hl(acc[mt][nt][2] * scale, acc[mt][nt][3] * scale, hh, ll);
                *reinterpret_cast<uint32_t*>(&Ch[(size_t)(m + 8) * D_ + n]) = hh;
                *reinterpret_cast<uint32_t*>(&Cl[(size_t)(m + 8) * D_ + n]) = ll;
            }
        }
}

// ---------------------------------------------------------------------------
// HMMA flash attention v2: Q kept in smem (reloaded via ldsm each stage) to
// cut registers -> 2 CTAs/SM; single __syncthreads per KV stage.
// ---------------------------------------------------------------------------
#define AKT 64
#define KROW 144
#define KB (AKT * KROW)            // 9216
#define QREG (128 * KROW)          // 18432 per hi/lo
#define KVBASE (2 * QREG)          // 36864
#define ASTG (4 * KB)              // 36864
#define ATT_SMEM (KVBASE + 2 * ASTG)   // 110592
#define NSKV (M_ / AKT)            // 32

__global__ __launch_bounds__(256, 2) void attn_mma()
{
    extern __shared__ char smem[];
    const uint32_t sb = smem_u32(smem);
    const int t = threadIdx.x;
    const int l = t & 31;
    const int w = t >> 5;
    const int q0 = blockIdx.x * 128;
    const int h  = blockIdx.y;
    const int b  = blockIdx.z;
    const size_t headoff = (size_t)h * DH_;

    // ---- Q (128x64 hi/lo) into persistent smem region
    #pragma unroll
    for (int i = 0; i < 4; i++) {
        int idx = i * 256 + t;
        int row = idx >> 3, ch = idx & 7;
        size_t g = (size_t)(b * N_ + q0 + row) * D_ + headoff + ch * 8;
        CP_ASYNC16(sb + row * KROW + ch * 16, g_qh + g);
        CP_ASYNC16(sb + QREG + row * KROW + ch * 16, g_ql + g);
    }
    CP_COMMIT();

    auto load_kv = [&](int s) {
        const int mk = s * AKT;
        const uint32_t base = sb + KVBASE + (s & 1) * ASTG;
        #pragma unroll
        for (int i = 0; i < 8; i++) {
            int arr = i >> 1;
            int rem = (i & 1) * 256 + t;
            int row = rem >> 3, ch = rem & 7;
            size_t g = (size_t)(b * M_ + mk + row) * D_ + headoff + ch * 8;
            const __nv_bfloat16* src = (arr == 0) ? g_kh : (arr == 1) ? g_kl
                                      : (arr == 2) ? g_vh : g_vl;
            CP_ASYNC16(base + arr * KB + row * KROW + ch * 16, src + g);
        }
        CP_COMMIT();
    };

    load_kv(0);
    CP_WAIT(0);
    __syncthreads();

    float o[8][4];
    #pragma unroll
    for (int j = 0; j < 8; j++)
        #pragma unroll
        for (int i = 0; i < 4; i++) o[j][i] = 0.f;
    float m0 = -1e30f, m1 = -1e30f, ls0 = 0.f, ls1 = 0.f;

    for (int s = 0; s < NSKV; s++) {
        if (s + 1 < NSKV) load_kv(s + 1);

        const uint32_t kh = sb + KVBASE + (s & 1) * ASTG;
        const uint32_t kl = kh + KB;
        const uint32_t vh = kh + 2 * KB;
        const uint32_t vl = kh + 3 * KB;

        // ---- S = Qh*Kh + Qh*Kl + Ql*Kh
        float sc[8][4];
        #pragma unroll
        for (int j = 0; j < 8; j++)
            #pragma unroll
            for (int i = 0; i < 4; i++) sc[j][i] = 0.f;

        #pragma unroll
        for (int ks = 0; ks < 4; ks++) {
            uint32_t qhf[4], qlf[4];
            {
                uint32_t qa = (uint32_t)((w * 16 + (l & 15)) * KROW + ks * 32 + (l >> 4) * 16);
                ldsm_x4(qhf, sb + qa);
                ldsm_x4(qlf, sb + QREG + qa);
            }
            int br = ((l >> 4) << 3) + (l & 7);
            int bcb = ks * 32 + ((l >> 3) & 1) * 16;
            #pragma unroll
            for (int nt2 = 0; nt2 < 4; nt2++) {
                uint32_t rh[4], rl[4];
                ldsm_x4(rh, kh + (uint32_t)((nt2 * 16 + br) * KROW + bcb));
                ldsm_x4(rl, kl + (uint32_t)((nt2 * 16 + br) * KROW + bcb));
                mma16816(sc[2 * nt2],     qhf, rh + 0);
                mma16816(sc[2 * nt2 + 1], qhf, rh + 2);
                mma16816(sc[2 * nt2],     qhf, rl + 0);
                mma16816(sc[2 * nt2 + 1], qhf, rl + 2);
                mma16816(sc[2 * nt2],     qlf, rh + 0);
                mma16816(sc[2 * nt2 + 1], qlf, rh + 2);
            }
        }

        // ---- online softmax (log2 domain)
        float mx0 = -1e30f, mx1 = -1e30f;
        #pragma unroll
        for (int j = 0; j < 8; j++) {
            mx0 = fmaxf(mx0, fmaxf(sc[j][0], sc[j][1]));
            mx1 = fmaxf(mx1, fmaxf(sc[j][2], sc[j][3]));
        }
        mx0 = fmaxf(mx0, __shfl_xor_sync(0xffffffffu, mx0, 1));
        mx0 = fmaxf(mx0, __shfl_xor_sync(0xffffffffu, mx0, 2));
        mx1 = fmaxf(mx1, __shfl_xor_sync(0xffffffffu, mx1, 1));
        mx1 = fmaxf(mx1, __shfl_xor_sync(0xffffffffu, mx1, 2));
        float mn0 = fmaxf(m0, mx0), mn1 = fmaxf(m1, mx1);
        float c0 = exp2f_fast(m0 - mn0), c1 = exp2f_fast(m1 - mn1);
        m0 = mn0; m1 = mn1;

        float ps0 = 0.f, ps1 = 0.f;
        #pragma unroll
        for (int j = 0; j < 8; j++) {
            sc[j][0] = exp2f_fast(sc[j][0] - mn0); ps0 += sc[j][0];
            sc[j][1] = exp2f_fast(sc[j][1] - mn0); ps0 += sc[j][1];
            sc[j][2] = exp2f_fast(sc[j][2] - mn1); ps1 += sc[j][2];
            sc[j][3] = exp2f_fast(sc[j][3] - mn1); ps1 += sc[j][3];
        }
        ps0 += __shfl_xor_sync(0xffffffffu, ps0, 1);
        ps0 += __shfl_xor_sync(0xffffffffu, ps0, 2);
        ps1 += __shfl_xor_sync(0xffffffffu, ps1, 1);
        ps1 += __shfl_xor_sync(0xffffffffu, ps1, 2);
        ls0 = ls0 * c0 + ps0;
        ls1 = ls1 * c1 + ps1;
        #pragma unroll
        for (int j = 0; j < 8; j++) {
            o[j][0] *= c0; o[j][1] *= c0;
            o[j][2] *= c1; o[j][3] *= c1;
        }

        // ---- O += (Ph+Pl) @ (Vh+Vl) (3 terms)
        #pragma unroll
        for (int kv = 0; kv < 4; kv++) {
            uint32_t aPh[4], aPl[4];
            pack_hl(sc[2 * kv][0],     sc[2 * kv][1],     aPh[0], aPl[0]);
            pack_hl(sc[2 * kv][2],     sc[2 * kv][3],     aPh[1], aPl[1]);
            pack_hl(sc[2 * kv + 1][0], sc[2 * kv + 1][1], aPh[2], aPl[2]);
            pack_hl(sc[2 * kv + 1][2], sc[2 * kv + 1][3], aPh[3], aPl[3]);
            int key = kv * 16 + ((l >> 3) & 1) * 8 + (l & 7);
            #pragma unroll
            for (int nd2 = 0; nd2 < 4; nd2++) {
                uint32_t vbh[4], vbl[4];
                uint32_t va = (uint32_t)(key * KROW + nd2 * 32 + (l >> 4) * 16);
                ldsm_x4_t(vbh, vh + va);
                ldsm_x4_t(vbl, vl + va);
                mma16816(o[2 * nd2],     aPh, vbh + 0);
                mma16816(o[2 * nd2 + 1], aPh, vbh + 2);
                mma16816(o[2 * nd2],     aPh, vbl + 0);
                mma16816(o[2 * nd2 + 1], aPh, vbl + 2);
                mma16816(o[2 * nd2],     aPl, vbh + 0);
                mma16816(o[2 * nd2 + 1], aPl, vbh + 2);
            }
        }

        if (s + 1 < NSKV) { CP_WAIT(0); __syncthreads(); }
    }

    // ---- normalize + write bf16 hi/lo
    float inv0 = 1.f / ls0, inv1 = 1.f / ls1;
    int r0 = q0 + w * 16 + (l >> 2);
    int r1 = r0 + 8;
    size_t base0 = (size_t)(b * N_ + r0) * D_ + headoff;
    size_t base1 = (size_t)(b * N_ + r1) * D_ + headoff;
    #pragma unroll
    for (int nd = 0; nd < 8; nd++) {
        int c = nd * 8 + (l & 3) * 2;
        uint32_t hh, ll;
        pack_hl(o[nd][0] * inv0, o[nd][1] * inv0, hh, ll);
        *reinterpret_cast<uint32_t*>(&g_oh[base0 + c]) = hh;
        *reinterpret_cast<uint32_t*>(&g_ol[base0 + c]) = ll;
        pack_hl(o[nd][2] * inv1, o[nd][3] * inv1, hh, ll);
        *reinterpret_cast<uint32_t*>(&g_oh[base1 + c]) = hh;
        *reinterpret_cast<uint32_t*>(&g_ol[base1 + c]) = ll;
    }
}

// ---------------------------------------------------------------------------
// Launch
// ---------------------------------------------------------------------------
extern "C" void kernel_launch(void* const* d_in, const int* in_sizes, int n_in,
                              void* d_out, int out_size)
{
    const float* x   = (const float*)d_in[0];
    const float* ctx = (const float*)d_in[1];
    const float* Wq  = (const float*)d_in[2];
    const float* Wk  = (const float*)d_in[3];
    const float* Wv  = (const float*)d_in[4];
    const float* Wo  = (const float*)d_in[5];
    const float* bo  = (const float*)d_in[6];
    float* out = (float*)d_out;

    __nv_bfloat16 *qh, *ql, *kh, *kl, *vh, *vl, *oh, *ol, *xh, *xl, *ch, *cl, *wh, *wl;
    cudaGetSymbolAddress((void**)&qh, g_qh); cudaGetSymbolAddress((void**)&ql, g_ql);
    cudaGetSymbolAddress((void**)&kh, g_kh); cudaGetSymbolAddress((void**)&kl, g_kl);
    cudaGetSymbolAddress((void**)&vh, g_vh); cudaGetSymbolAddress((void**)&vl, g_vl);
    cudaGetSymbolAddress((void**)&oh, g_oh); cudaGetSymbolAddress((void**)&ol, g_ol);
    cudaGetSymbolAddress((void**)&xh, g_xh); cudaGetSymbolAddress((void**)&xl, g_xl);
    cudaGetSymbolAddress((void**)&ch, g_ch); cudaGetSymbolAddress((void**)&cl, g_cl);
    cudaGetSymbolAddress((void**)&wh, g_wh); cudaGetSymbolAddress((void**)&wl, g_wl);

    cudaFuncSetAttribute(hmma_gemm<0>, cudaFuncAttributeMaxDynamicSharedMemorySize, GEMM_SMEM);
    cudaFuncSetAttribute(hmma_gemm<1>, cudaFuncAttributeMaxDynamicSharedMemorySize, GEMM_SMEM);
    cudaFuncSetAttribute(attn_mma, cudaFuncAttributeMaxDynamicSharedMemorySize, ATT_SMEM);

    const int NE = ROWS_ * D_;

    split2_kernel<<<dim3((NE + 255) / 256, 2), 256>>>(x, ctx, xh, xl, ch, cl, NE);
    wsplit_t_kernel<<<dim3(32, 32, 4), dim3(32, 32)>>>(Wq, Wk, Wv, Wo, wh, wl);

    // fused Q/K/V projections: grid.z = 0,1,2
    hmma_gemm<1><<<dim3(D_ / 128, ROWS_ / 128, 3), 128, GEMM_SMEM>>>(
        xh, xl, ch, cl, wh, wl, nullptr, nullptr, qh, ql, kh, kl, vh, vl);

    attn_mma<<<dim3(N_ / 128, H_, B_), 256, ATT_SMEM>>>();

    hmma_gemm<0><<<dim3(D_ / 128, ROWS_ / 128, 1), 128, GEMM_SMEM>>>(
        oh, ol, nullptr, nullptr, wh, wl, bo, out,
        nullptr, nullptr, nullptr, nullptr, nullptr, nullptr);
}